// round 16
// baseline (speedup 1.0000x reference)
#include <cuda_runtime.h>

// Problem constants
#define GHN 16
#define GWN 16
#define GD  8
#define NCH 12          // NIN*NOUT coefficients per depth bin
#define CELLF 96        // GD*NCH floats per grid cell
#define HIMG 1024
#define WIMG 1024
#define BATCH 4

// Grid buffer: [b][gh*16+gw][z*12+c]  (4 * 256 * 96 floats = 393KB)
__device__ float g_grid[BATCH * 256 * CELLF];

// ---------------------------------------------------------------------------
// Kernel 0: build the bilateral grid.
// x[b, cout, cell] = fusion_b[cout] + sum_j fusion_w[cout,j] * relu(local[b,j,cell] + global[b,j])
// grid[b, gh, gw, z, c] = x[b, z*12+c, gh, gw]  -> cout == z*12+c directly.
// One thread per (b, cell, cout): 4*256*96 = 98304 threads.
// ---------------------------------------------------------------------------
__global__ void grid_kernel(const float* __restrict__ local_f,
                            const float* __restrict__ global_f,
                            const float* __restrict__ fw,
                            const float* __restrict__ fb)
{
    int idx  = blockIdx.x * blockDim.x + threadIdx.x;
    int cout = idx % CELLF;
    int t    = idx / CELLF;
    int cell = t % 256;
    int b    = t / 256;
    if (b >= BATCH) return;

    float acc = fb[cout];
    const float* wrow = fw + cout * 64;
    const float* lf   = local_f + (size_t)b * 64 * 256 + cell;
    const float* gf   = global_f + b * 64;
#pragma unroll 8
    for (int j = 0; j < 64; j++) {
        float v = lf[j * 256] + gf[j];
        v = fmaxf(v, 0.0f);
        acc = fmaf(wrow[j], v, acc);
    }
    g_grid[((size_t)b * 256 + cell) * CELLF + cout] = acc;
}

// ---------------------------------------------------------------------------
// Kernel 1: fused guide MLP + bilateral slice + apply + tanh.
// Grid: (16, 16, 4) CTAs; each CTA handles a 64x64 pixel tile (one grid cell
// wide in each dim), staging the 3x3 neighboring cells into smem (3456 B).
// Block: (16, 8) = 128 threads; each thread: 4 consecutive w-pixels (float4
// vector IO) x 8 rows (stride 8).
// ---------------------------------------------------------------------------
__global__ __launch_bounds__(128) void slice_kernel(
    const float* __restrict__ fullres,
    const float* __restrict__ g1w, const float* __restrict__ g1b,
    const float* __restrict__ bng, const float* __restrict__ bnb,
    const float* __restrict__ bnm, const float* __restrict__ bnv,
    const float* __restrict__ g2w, const float* __restrict__ g2b,
    float* __restrict__ out)
{
    __shared__ float sg[9 * CELLF];   // 3x3 cells, clip-replicated at borders

    const int s = blockIdx.x;   // w tile / cell
    const int r = blockIdx.y;   // h tile / cell
    const int b = blockIdx.z;
    const int tid = threadIdx.y * 16 + threadIdx.x;

    // ---- stage 3x3 grid cells (clipped) into smem ----
    for (int i = tid; i < 9 * CELLF; i += 128) {
        int ci = i / CELLF;
        int e  = i - ci * CELLF;
        int gh = min(max(r - 1 + ci / 3, 0), GHN - 1);
        int gw = min(max(s - 1 + ci % 3, 0), GWN - 1);
        sg[i] = g_grid[((size_t)b * 256 + gh * GWN + gw) * CELLF + e];
    }

    // ---- guide weights, BN folded, in registers ----
    float w1r[16], w1g[16], w1b[16], bb1[16], w2[16];
#pragma unroll
    for (int j = 0; j < 16; j++) {
        float sc = bng[j] * rsqrtf(bnv[j] + 1e-5f);
        w1r[j] = g1w[j * 3 + 0] * sc;
        w1g[j] = g1w[j * 3 + 1] * sc;
        w1b[j] = g1w[j * 3 + 2] * sc;
        bb1[j] = (g1b[j] - bnm[j]) * sc + bnb[j];
        w2[j]  = g2w[j];
    }
    const float b2 = g2b[0];

    __syncthreads();

    // ---- per-thread w coordinates (4 consecutive pixels) ----
    const int wbase = s * 64 + threadIdx.x * 4;
    float fw_[4];
    int   wl0_[4];
#pragma unroll
    for (int k = 0; k < 4; k++) {
        float wgf = (wbase + k + 0.5f) * 0.015625f - 0.5f;  // *16/1024
        float w0  = floorf(wgf);
        fw_[k]  = wgf - w0;
        wl0_[k] = (int)w0 - s + 1;   // local cell index in [0,1]
    }

    const float* fr = fullres + (size_t)b * 3 * (HIMG * (size_t)WIMG);
    float*       op = out     + (size_t)b * 3 * (HIMG * (size_t)WIMG);
    const size_t PL = (size_t)HIMG * WIMG;

    for (int rr = 0; rr < 8; rr++) {
        const int row = threadIdx.y + rr * 8;
        const int h   = r * 64 + row;
        float hgf = (h + 0.5f) * 0.015625f - 0.5f;
        float h0  = floorf(hgf);
        float fh  = hgf - h0;
        int   hl0 = (int)h0 - r + 1;   // local cell index in [0,1]
        float wh0 = 1.0f - fh;

        const size_t pofs = (size_t)h * WIMG + wbase;
        float4 R4 = *(const float4*)(fr + pofs);
        float4 G4 = *(const float4*)(fr + PL + pofs);
        float4 B4 = *(const float4*)(fr + 2 * PL + pofs);

        float rv[4] = {R4.x, R4.y, R4.z, R4.w};
        float gv[4] = {G4.x, G4.y, G4.z, G4.w};
        float bv[4] = {B4.x, B4.y, B4.z, B4.w};
        float oR[4], oG[4], oB[4];

#pragma unroll
        for (int k = 0; k < 4; k++) {
            const float pr = rv[k], pg = gv[k], pb = bv[k];

            // ---- guide MLP ----
            float a = b2;
#pragma unroll
            for (int j = 0; j < 16; j++) {
                float hd = fmaf(w1r[j], pr, fmaf(w1g[j], pg, fmaf(w1b[j], pb, bb1[j])));
                hd = fmaxf(hd, 0.0f);
                a = fmaf(w2[j], hd, a);
            }
            float guide = __fdividef(1.0f, 1.0f + __expf(-a));

            // ---- z coords ----
            float zg  = guide * 8.0f - 0.5f;
            float z0f = floorf(zg);
            float fz  = zg - z0f;
            int   iz  = (int)z0f;
            int   iz0 = min(max(iz, 0), GD - 1);
            int   iz1 = min(iz + 1, GD - 1);
            float wz0 = 1.0f - fz, wz1 = fz;

            // ---- trilinear gather of 12 coeffs ----
            const float fwk = fw_[k];
            const float ww0 = 1.0f - fwk;
            const int cbase = (hl0 * 3 + wl0_[k]) * CELLF;
            const int zo0 = iz0 * NCH, zo1 = iz1 * NCH;

            float acc[12];
#pragma unroll
            for (int c = 0; c < 12; c++) acc[c] = 0.0f;

#pragma unroll
            for (int dh = 0; dh < 2; dh++) {
                const float whh = dh ? fh : wh0;
#pragma unroll
                for (int dw = 0; dw < 2; dw++) {
                    const float whw = whh * (dw ? fwk : ww0);
                    const int cofs = cbase + (dh * 3 + dw) * CELLF;
                    const float w0c = whw * wz0;
                    const float w1c = whw * wz1;
                    const float4* p0 = (const float4*)(sg + cofs + zo0);
                    const float4* p1 = (const float4*)(sg + cofs + zo1);
                    float4 a0 = p0[0], a1 = p0[1], a2 = p0[2];
                    float4 c0 = p1[0], c1 = p1[1], c2 = p1[2];
                    acc[0]  = fmaf(w0c, a0.x, fmaf(w1c, c0.x, acc[0]));
                    acc[1]  = fmaf(w0c, a0.y, fmaf(w1c, c0.y, acc[1]));
                    acc[2]  = fmaf(w0c, a0.z, fmaf(w1c, c0.z, acc[2]));
                    acc[3]  = fmaf(w0c, a0.w, fmaf(w1c, c0.w, acc[3]));
                    acc[4]  = fmaf(w0c, a1.x, fmaf(w1c, c1.x, acc[4]));
                    acc[5]  = fmaf(w0c, a1.y, fmaf(w1c, c1.y, acc[5]));
                    acc[6]  = fmaf(w0c, a1.z, fmaf(w1c, c1.z, acc[6]));
                    acc[7]  = fmaf(w0c, a1.w, fmaf(w1c, c1.w, acc[7]));
                    acc[8]  = fmaf(w0c, a2.x, fmaf(w1c, c2.x, acc[8]));
                    acc[9]  = fmaf(w0c, a2.y, fmaf(w1c, c2.y, acc[9]));
                    acc[10] = fmaf(w0c, a2.z, fmaf(w1c, c2.z, acc[10]));
                    acc[11] = fmaf(w0c, a2.w, fmaf(w1c, c2.w, acc[11]));
                }
            }

            // ---- apply color transform + tanh ----
            float Rv = fmaf(pr, acc[0], fmaf(pg, acc[1], fmaf(pb, acc[2],  acc[9])));
            float Gv = fmaf(pr, acc[3], fmaf(pg, acc[4], fmaf(pb, acc[5],  acc[10])));
            float Bv = fmaf(pr, acc[6], fmaf(pg, acc[7], fmaf(pb, acc[8],  acc[11])));

            // tanh(x) = (e^{2x}-1)/(e^{2x}+1), clamped to avoid overflow
            float xr = fminf(fmaxf(Rv, -10.0f), 10.0f);
            float xg = fminf(fmaxf(Gv, -10.0f), 10.0f);
            float xb = fminf(fmaxf(Bv, -10.0f), 10.0f);
            float er = __expf(2.0f * xr);
            float eg = __expf(2.0f * xg);
            float eb = __expf(2.0f * xb);
            oR[k] = __fdividef(er - 1.0f, er + 1.0f);
            oG[k] = __fdividef(eg - 1.0f, eg + 1.0f);
            oB[k] = __fdividef(eb - 1.0f, eb + 1.0f);
        }

        float4 vR = make_float4(oR[0], oR[1], oR[2], oR[3]);
        float4 vG = make_float4(oG[0], oG[1], oG[2], oG[3]);
        float4 vB = make_float4(oB[0], oB[1], oB[2], oB[3]);
        *(float4*)(op + pofs)          = vR;
        *(float4*)(op + PL + pofs)     = vG;
        *(float4*)(op + 2 * PL + pofs) = vB;
    }
}

// ---------------------------------------------------------------------------
// Input order (metadata): 0 fullres, 1 local_features, 2 global_features,
// 3 fusion_w, 4 fusion_b, 5 g1_w, 6 g1_b, 7 bn_gamma, 8 bn_beta, 9 bn_mean,
// 10 bn_var, 11 g2_w, 12 g2_b
// ---------------------------------------------------------------------------
extern "C" void kernel_launch(void* const* d_in, const int* in_sizes, int n_in,
                              void* d_out, int out_size)
{
    const float* fullres  = (const float*)d_in[0];
    const float* local_f  = (const float*)d_in[1];
    const float* global_f = (const float*)d_in[2];
    const float* fusion_w = (const float*)d_in[3];
    const float* fusion_b = (const float*)d_in[4];
    const float* g1_w     = (const float*)d_in[5];
    const float* g1_b     = (const float*)d_in[6];
    const float* bn_gamma = (const float*)d_in[7];
    const float* bn_beta  = (const float*)d_in[8];
    const float* bn_mean  = (const float*)d_in[9];
    const float* bn_var   = (const float*)d_in[10];
    const float* g2_w     = (const float*)d_in[11];
    const float* g2_b     = (const float*)d_in[12];
    float* out = (float*)d_out;

    // Kernel 0: 4*256*96 = 98304 threads
    grid_kernel<<<384, 256>>>(local_f, global_f, fusion_w, fusion_b);

    // Kernel 1: 16x16x4 tiles of 64x64 pixels
    dim3 grid(16, 16, 4);
    dim3 block(16, 8);
    slice_kernel<<<grid, block>>>(fullres, g1_w, g1_b,
                                  bn_gamma, bn_beta, bn_mean, bn_var,
                                  g2_w, g2_b, out);
}

// round 17
// speedup vs baseline: 1.0014x; 1.0014x over previous
#include <cuda_runtime.h>

// Problem constants
#define GHN 16
#define GWN 16
#define GD  8
#define NCH 12          // NIN*NOUT coefficients per depth bin
#define CELLF 96        // GD*NCH floats per grid cell
#define HIMG 1024
#define WIMG 1024
#define BATCH 4

// Grid buffer: [b][gh*16+gw][z*12+c]  (4 * 256 * 96 floats = 393KB)
__device__ float g_grid[BATCH * 256 * CELLF];

// ---------------------------------------------------------------------------
// Kernel 0: build the bilateral grid.
// x[b, cout, cell] = fusion_b[cout] + sum_j fusion_w[cout,j] * relu(local[b,j,cell] + global[b,j])
// grid[b, gh, gw, z, c] = x[b, z*12+c, gh, gw]  -> cout == z*12+c directly.
// One thread per (b, cell, cout): 4*256*96 = 98304 threads.
// ---------------------------------------------------------------------------
__global__ void grid_kernel(const float* __restrict__ local_f,
                            const float* __restrict__ global_f,
                            const float* __restrict__ fw,
                            const float* __restrict__ fb)
{
    int idx  = blockIdx.x * blockDim.x + threadIdx.x;
    int cout = idx % CELLF;
    int t    = idx / CELLF;
    int cell = t % 256;
    int b    = t / 256;
    if (b >= BATCH) return;

    float acc = fb[cout];
    const float* wrow = fw + cout * 64;
    const float* lf   = local_f + (size_t)b * 64 * 256 + cell;
    const float* gf   = global_f + b * 64;
#pragma unroll 8
    for (int j = 0; j < 64; j++) {
        float v = lf[j * 256] + gf[j];
        v = fmaxf(v, 0.0f);
        acc = fmaf(wrow[j], v, acc);
    }
    g_grid[((size_t)b * 256 + cell) * CELLF + cout] = acc;
}

// ---------------------------------------------------------------------------
// Kernel 1: fused guide MLP + bilateral slice + apply + tanh.
// Grid: (16, 16, 4) CTAs; each CTA handles a 64x64 pixel tile (one grid cell
// wide in each dim), staging the 3x3 neighboring cells into smem (3456 B).
// Block: (16, 8) = 128 threads; each thread: 4 consecutive w-pixels (float4
// vector IO) x 8 rows (stride 8).
// ---------------------------------------------------------------------------
__global__ __launch_bounds__(128) void slice_kernel(
    const float* __restrict__ fullres,
    const float* __restrict__ g1w, const float* __restrict__ g1b,
    const float* __restrict__ bng, const float* __restrict__ bnb,
    const float* __restrict__ bnm, const float* __restrict__ bnv,
    const float* __restrict__ g2w, const float* __restrict__ g2b,
    float* __restrict__ out)
{
    __shared__ float sg[9 * CELLF];   // 3x3 cells, clip-replicated at borders

    const int s = blockIdx.x;   // w tile / cell
    const int r = blockIdx.y;   // h tile / cell
    const int b = blockIdx.z;
    const int tid = threadIdx.y * 16 + threadIdx.x;

    // ---- stage 3x3 grid cells (clipped) into smem ----
    for (int i = tid; i < 9 * CELLF; i += 128) {
        int ci = i / CELLF;
        int e  = i - ci * CELLF;
        int gh = min(max(r - 1 + ci / 3, 0), GHN - 1);
        int gw = min(max(s - 1 + ci % 3, 0), GWN - 1);
        sg[i] = g_grid[((size_t)b * 256 + gh * GWN + gw) * CELLF + e];
    }

    // ---- guide weights, BN folded, in registers ----
    float w1r[16], w1g[16], w1b[16], bb1[16], w2[16];
#pragma unroll
    for (int j = 0; j < 16; j++) {
        float sc = bng[j] * rsqrtf(bnv[j] + 1e-5f);
        w1r[j] = g1w[j * 3 + 0] * sc;
        w1g[j] = g1w[j * 3 + 1] * sc;
        w1b[j] = g1w[j * 3 + 2] * sc;
        bb1[j] = (g1b[j] - bnm[j]) * sc + bnb[j];
        w2[j]  = g2w[j];
    }
    const float b2 = g2b[0];

    __syncthreads();

    // ---- per-thread w coordinates (4 consecutive pixels) ----
    const int wbase = s * 64 + threadIdx.x * 4;
    float fw_[4];
    int   wl0_[4];
#pragma unroll
    for (int k = 0; k < 4; k++) {
        float wgf = (wbase + k + 0.5f) * 0.015625f - 0.5f;  // *16/1024
        float w0  = floorf(wgf);
        fw_[k]  = wgf - w0;
        wl0_[k] = (int)w0 - s + 1;   // local cell index in [0,1]
    }

    const float* fr = fullres + (size_t)b * 3 * (HIMG * (size_t)WIMG);
    float*       op = out     + (size_t)b * 3 * (HIMG * (size_t)WIMG);
    const size_t PL = (size_t)HIMG * WIMG;

    for (int rr = 0; rr < 8; rr++) {
        const int row = threadIdx.y + rr * 8;
        const int h   = r * 64 + row;
        float hgf = (h + 0.5f) * 0.015625f - 0.5f;
        float h0  = floorf(hgf);
        float fh  = hgf - h0;
        int   hl0 = (int)h0 - r + 1;   // local cell index in [0,1]
        float wh0 = 1.0f - fh;

        const size_t pofs = (size_t)h * WIMG + wbase;
        float4 R4 = *(const float4*)(fr + pofs);
        float4 G4 = *(const float4*)(fr + PL + pofs);
        float4 B4 = *(const float4*)(fr + 2 * PL + pofs);

        float rv[4] = {R4.x, R4.y, R4.z, R4.w};
        float gv[4] = {G4.x, G4.y, G4.z, G4.w};
        float bv[4] = {B4.x, B4.y, B4.z, B4.w};
        float oR[4], oG[4], oB[4];

#pragma unroll
        for (int k = 0; k < 4; k++) {
            const float pr = rv[k], pg = gv[k], pb = bv[k];

            // ---- guide MLP ----
            float a = b2;
#pragma unroll
            for (int j = 0; j < 16; j++) {
                float hd = fmaf(w1r[j], pr, fmaf(w1g[j], pg, fmaf(w1b[j], pb, bb1[j])));
                hd = fmaxf(hd, 0.0f);
                a = fmaf(w2[j], hd, a);
            }
            float guide = __fdividef(1.0f, 1.0f + __expf(-a));

            // ---- z coords ----
            float zg  = guide * 8.0f - 0.5f;
            float z0f = floorf(zg);
            float fz  = zg - z0f;
            int   iz  = (int)z0f;
            int   iz0 = min(max(iz, 0), GD - 1);
            int   iz1 = min(iz + 1, GD - 1);
            float wz0 = 1.0f - fz, wz1 = fz;

            // ---- trilinear gather of 12 coeffs ----
            const float fwk = fw_[k];
            const float ww0 = 1.0f - fwk;
            const int cbase = (hl0 * 3 + wl0_[k]) * CELLF;
            const int zo0 = iz0 * NCH, zo1 = iz1 * NCH;

            float acc[12];
#pragma unroll
            for (int c = 0; c < 12; c++) acc[c] = 0.0f;

#pragma unroll
            for (int dh = 0; dh < 2; dh++) {
                const float whh = dh ? fh : wh0;
#pragma unroll
                for (int dw = 0; dw < 2; dw++) {
                    const float whw = whh * (dw ? fwk : ww0);
                    const int cofs = cbase + (dh * 3 + dw) * CELLF;
                    const float w0c = whw * wz0;
                    const float w1c = whw * wz1;
                    const float4* p0 = (const float4*)(sg + cofs + zo0);
                    const float4* p1 = (const float4*)(sg + cofs + zo1);
                    float4 a0 = p0[0], a1 = p0[1], a2 = p0[2];
                    float4 c0 = p1[0], c1 = p1[1], c2 = p1[2];
                    acc[0]  = fmaf(w0c, a0.x, fmaf(w1c, c0.x, acc[0]));
                    acc[1]  = fmaf(w0c, a0.y, fmaf(w1c, c0.y, acc[1]));
                    acc[2]  = fmaf(w0c, a0.z, fmaf(w1c, c0.z, acc[2]));
                    acc[3]  = fmaf(w0c, a0.w, fmaf(w1c, c0.w, acc[3]));
                    acc[4]  = fmaf(w0c, a1.x, fmaf(w1c, c1.x, acc[4]));
                    acc[5]  = fmaf(w0c, a1.y, fmaf(w1c, c1.y, acc[5]));
                    acc[6]  = fmaf(w0c, a1.z, fmaf(w1c, c1.z, acc[6]));
                    acc[7]  = fmaf(w0c, a1.w, fmaf(w1c, c1.w, acc[7]));
                    acc[8]  = fmaf(w0c, a2.x, fmaf(w1c, c2.x, acc[8]));
                    acc[9]  = fmaf(w0c, a2.y, fmaf(w1c, c2.y, acc[9]));
                    acc[10] = fmaf(w0c, a2.z, fmaf(w1c, c2.z, acc[10]));
                    acc[11] = fmaf(w0c, a2.w, fmaf(w1c, c2.w, acc[11]));
                }
            }

            // ---- apply color transform + tanh ----
            float Rv = fmaf(pr, acc[0], fmaf(pg, acc[1], fmaf(pb, acc[2],  acc[9])));
            float Gv = fmaf(pr, acc[3], fmaf(pg, acc[4], fmaf(pb, acc[5],  acc[10])));
            float Bv = fmaf(pr, acc[6], fmaf(pg, acc[7], fmaf(pb, acc[8],  acc[11])));

            // tanh(x) = (e^{2x}-1)/(e^{2x}+1), clamped to avoid overflow
            float xr = fminf(fmaxf(Rv, -10.0f), 10.0f);
            float xg = fminf(fmaxf(Gv, -10.0f), 10.0f);
            float xb = fminf(fmaxf(Bv, -10.0f), 10.0f);
            float er = __expf(2.0f * xr);
            float eg = __expf(2.0f * xg);
            float eb = __expf(2.0f * xb);
            oR[k] = __fdividef(er - 1.0f, er + 1.0f);
            oG[k] = __fdividef(eg - 1.0f, eg + 1.0f);
            oB[k] = __fdividef(eb - 1.0f, eb + 1.0f);
        }

        float4 vR = make_float4(oR[0], oR[1], oR[2], oR[3]);
        float4 vG = make_float4(oG[0], oG[1], oG[2], oG[3]);
        float4 vB = make_float4(oB[0], oB[1], oB[2], oB[3]);
        *(float4*)(op + pofs)          = vR;
        *(float4*)(op + PL + pofs)     = vG;
        *(float4*)(op + 2 * PL + pofs) = vB;
    }
}

// ---------------------------------------------------------------------------
// Input order (metadata): 0 fullres, 1 local_features, 2 global_features,
// 3 fusion_w, 4 fusion_b, 5 g1_w, 6 g1_b, 7 bn_gamma, 8 bn_beta, 9 bn_mean,
// 10 bn_var, 11 g2_w, 12 g2_b
// ---------------------------------------------------------------------------
extern "C" void kernel_launch(void* const* d_in, const int* in_sizes, int n_in,
                              void* d_out, int out_size)
{
    const float* fullres  = (const float*)d_in[0];
    const float* local_f  = (const float*)d_in[1];
    const float* global_f = (const float*)d_in[2];
    const float* fusion_w = (const float*)d_in[3];
    const float* fusion_b = (const float*)d_in[4];
    const float* g1_w     = (const float*)d_in[5];
    const float* g1_b     = (const float*)d_in[6];
    const float* bn_gamma = (const float*)d_in[7];
    const float* bn_beta  = (const float*)d_in[8];
    const float* bn_mean  = (const float*)d_in[9];
    const float* bn_var   = (const float*)d_in[10];
    const float* g2_w     = (const float*)d_in[11];
    const float* g2_b     = (const float*)d_in[12];
    float* out = (float*)d_out;

    // Kernel 0: 4*256*96 = 98304 threads
    grid_kernel<<<384, 256>>>(local_f, global_f, fusion_w, fusion_b);

    // Kernel 1: 16x16x4 tiles of 64x64 pixels
    dim3 grid(16, 16, 4);
    dim3 block(16, 8);
    slice_kernel<<<grid, block>>>(fullres, g1_w, g1_b,
                                  bn_gamma, bn_beta, bn_mean, bn_var,
                                  g2_w, g2_b, out);
}